// round 3
// baseline (speedup 1.0000x reference)
#include <cuda_runtime.h>
#include <math.h>

#define B_ 4
#define S_ 4096
#define H_ 2048
#define E_ 16
#define ED_ 512
#define H4 (H_/4)          // 512 float4 per row
#define NBLK_A 512
#define WARPS_A 4          // per block
#define ROWS_PER_WARP 8    // 512*4*8 = 16384 = B*S
#define BLKS_PER_BATCH (NBLK_A / B_)   // 128

// ---------------- device scratch (written fresh every launch) ----------------
__device__ float g_part[NBLK_A * H_];   // per-block LN partial sums (4 MB)
__device__ float g_qi[B_ * H_];         // query_input
__device__ float g_lf[E_ * H_];         // layer_features
__device__ float g_q[B_ * H_];          // q
__device__ float g_k[E_ * H_];          // k

__device__ __forceinline__ float warp_sum(float v) {
#pragma unroll
    for (int o = 16; o > 0; o >>= 1) v += __shfl_xor_sync(0xffffffffu, v, o);
    return v;
}
__device__ __forceinline__ float dot4(float4 a, float4 b) {
    return fmaf(a.x, b.x, fmaf(a.y, b.y, fmaf(a.z, b.z, a.w * b.w)));
}

// ---------------- Kernel A: LayerNorm + mean over S (partials) ----------------
__global__ void __launch_bounds__(128) kA(const float* __restrict__ hid) {
    __shared__ float sbuf[WARPS_A * H_];   // 32 KB
    const int warp = threadIdx.x >> 5, lane = threadIdx.x & 31;
    const long wg = (long)blockIdx.x * WARPS_A + warp;       // 0..2047
    const size_t row0 = (size_t)wg * ROWS_PER_WARP;

    float4 acc[16];
#pragma unroll
    for (int i = 0; i < 16; i++) acc[i] = make_float4(0.f, 0.f, 0.f, 0.f);

    for (int r = 0; r < ROWS_PER_WARP; r++) {
        const float4* p = reinterpret_cast<const float4*>(hid) + (row0 + r) * H4;
        float4 v[16];
        float s = 0.f, s2 = 0.f;
#pragma unroll
        for (int i = 0; i < 16; i++) {
            float4 t = p[i * 32 + lane];
            v[i] = t;
            s  += t.x + t.y + t.z + t.w;
            s2 += t.x * t.x + t.y * t.y + t.z * t.z + t.w * t.w;
        }
        s = warp_sum(s); s2 = warp_sum(s2);
        const float mu = s * (1.f / H_);
        const float var = s2 * (1.f / H_) - mu * mu;
        const float rr = rsqrtf(var + 1e-5f);
#pragma unroll
        for (int i = 0; i < 16; i++) {
            acc[i].x += (v[i].x - mu) * rr;
            acc[i].y += (v[i].y - mu) * rr;
            acc[i].z += (v[i].z - mu) * rr;
            acc[i].w += (v[i].w - mu) * rr;
        }
    }
    // stage per-warp partials in smem
    float4* sb4 = reinterpret_cast<float4*>(sbuf) + warp * H4;
#pragma unroll
    for (int i = 0; i < 16; i++) sb4[i * 32 + lane] = acc[i];
    __syncthreads();
    // reduce 4 warps -> g_part[blk]
    float4* out4 = reinterpret_cast<float4*>(g_part + (size_t)blockIdx.x * H_);
    const float4* sall = reinterpret_cast<const float4*>(sbuf);
    for (int i = threadIdx.x; i < H4; i += 128) {
        float4 a = sall[i], b = sall[H4 + i], c = sall[2 * H4 + i], d = sall[3 * H4 + i];
        out4[i] = make_float4(a.x + b.x + c.x + d.x, a.y + b.y + c.y + d.y,
                              a.z + b.z + c.z + d.z, a.w + b.w + c.w + d.w);
    }
}

// ---------------- Kernel B0: reduce partials -> query_input; build lf ----------------
__global__ void __launch_bounds__(256) kB0(const float* __restrict__ le,
                                           const float* __restrict__ ce,
                                           const float* __restrict__ gamma,
                                           const float* __restrict__ beta,
                                           const int* __restrict__ curp) {
    const int blk = blockIdx.x;
    if (blk < 32) {
        // query_input: 8192 elements
        int idx = blk * 256 + threadIdx.x;       // b*H + h
        int b = idx >> 11, h = idx & (H_ - 1);
        float s = 0.f;
        const float* base = g_part + (size_t)(b * BLKS_PER_BATCH) * H_ + h;
#pragma unroll 4
        for (int c = 0; c < BLKS_PER_BATCH; c++) s += base[(size_t)c * H_];
        int cur = *curp;
        g_qi[idx] = le[cur * H_ + h] + gamma[h] * (s * (1.f / S_)) + beta[h];
    } else {
        int idx = (blk - 32) * 256 + threadIdx.x;  // 0..32767
        g_lf[idx] = le[idx] + ce[idx];
    }
}

// ---------------- Kernel B: fused q/k GEMV (warp per 2 output columns) ----------------
__global__ void __launch_bounds__(256) kB(const float* __restrict__ Wq,
                                          const float* __restrict__ bq,
                                          const float* __restrict__ Wk,
                                          const float* __restrict__ bk) {
    const int warp = threadIdx.x >> 5, lane = threadIdx.x & 31;
    const int wg = blockIdx.x * 8 + warp;        // 0..1023
    const int j0 = wg * 2;

    float aq0[B_], aq1[B_], ak0[E_], ak1[E_];
#pragma unroll
    for (int b = 0; b < B_; b++) { aq0[b] = 0.f; aq1[b] = 0.f; }
#pragma unroll
    for (int e = 0; e < E_; e++) { ak0[e] = 0.f; ak1[e] = 0.f; }

    const float4* wq0 = reinterpret_cast<const float4*>(Wq) + (size_t)j0 * H4;
    const float4* wq1 = wq0 + H4;
    const float4* wk0 = reinterpret_cast<const float4*>(Wk) + (size_t)j0 * H4;
    const float4* wk1 = wk0 + H4;
    const float4* qi = reinterpret_cast<const float4*>(g_qi);
    const float4* lf = reinterpret_cast<const float4*>(g_lf);

#pragma unroll 4
    for (int t = 0; t < 16; t++) {
        const int idx = t * 32 + lane;
        float4 a0 = wq0[idx], a1 = wq1[idx];
        float4 c0 = wk0[idx], c1 = wk1[idx];
#pragma unroll
        for (int b = 0; b < B_; b++) {
            float4 x = qi[b * H4 + idx];
            aq0[b] += dot4(a0, x);
            aq1[b] += dot4(a1, x);
        }
#pragma unroll
        for (int e = 0; e < E_; e++) {
            float4 x = lf[e * H4 + idx];
            ak0[e] += dot4(c0, x);
            ak1[e] += dot4(c1, x);
        }
    }
#pragma unroll
    for (int b = 0; b < B_; b++) {
        float s0 = warp_sum(aq0[b]), s1 = warp_sum(aq1[b]);
        if (lane == 0) { g_q[b * H_ + j0] = s0 + bq[j0]; g_q[b * H_ + j0 + 1] = s1 + bq[j0 + 1]; }
    }
#pragma unroll
    for (int e = 0; e < E_; e++) {
        float s0 = warp_sum(ak0[e]), s1 = warp_sum(ak1[e]);
        if (lane == 0) { g_k[e * H_ + j0] = s0 + bk[j0]; g_k[e * H_ + j0 + 1] = s1 + bk[j0 + 1]; }
    }
}

// ---------------- Kernel C: epilogue (1 block) ----------------
__global__ void __launch_bounds__(256) kC(const float* __restrict__ spatial,
                                          const float* __restrict__ edge,
                                          const int* __restrict__ curp,
                                          const int* __restrict__ avail,
                                          float* __restrict__ out) {
    __shared__ float s_att[B_ * E_];
    __shared__ float s_w[ED_];
    __shared__ float s_eb[E_];
    __shared__ float s_sb[E_];
    const int tid = threadIdx.x, warp = tid >> 5, lane = tid & 31;
    const int cur = *curp;

    // attention[b][e] = q[b] . k[e] / sqrt(H); 8 warps x 8 outputs
    const float4* q4 = reinterpret_cast<const float4*>(g_q);
    const float4* k4 = reinterpret_cast<const float4*>(g_k);
    const float inv_sqrt_h = rsqrtf((float)H_);
    for (int oo = 0; oo < 8; oo++) {
        int o = warp * 8 + oo;
        int b = o >> 4, e = o & 15;
        float s = 0.f;
#pragma unroll
        for (int t = 0; t < 16; t++) {
            float4 a = q4[b * H4 + t * 32 + lane];
            float4 c = k4[e * H4 + t * 32 + lane];
            s += dot4(a, c);
        }
        s = warp_sum(s);
        if (lane == 0) s_att[o] = s * inv_sqrt_h;
    }

    // edge weight vector: w = sum_i row_mask_i * scale_i * edge[i,:]
    for (int h = tid; h < ED_; h += 256) {
        float a = 0.f;
#pragma unroll
        for (int i = 0; i < E_; i++) {
            int d = abs(i - cur);
            float rm = (float)avail[i] * ((i != cur) ? 1.f : 0.f) * (1.f / (float)max(d, 1));
            a += rm * edge[i * ED_ + h];
        }
        s_w[h] = a;
    }
    if (tid < E_) s_sb[tid] = spatial[abs(tid - cur)];
    __syncthreads();

    // edge_bias[j] = w . edge[j,:]; 8 warps x 2 outputs
    for (int jj = 0; jj < 2; jj++) {
        int j = warp * 2 + jj;
        float s = 0.f;
#pragma unroll
        for (int t = 0; t < 16; t++) s += s_w[t * 32 + lane] * edge[j * ED_ + t * 32 + lane];
        s = warp_sum(s);
        if (lane == 0) s_eb[j] = s;
    }
    __syncthreads();

    // finalize on warp 0
    if (warp == 0) {
        float av = (lane < E_) ? (float)avail[lane] : 0.f;
        float num_avail = warp_sum(av);
        float tprob = 1.f / num_avail;
        float logt = logf(tprob);
        float klacc = 0.f;
        int nidx = 0;
        for (int b = 0; b < B_; b++) {
            float sc = -1e30f;
            bool ok = false;
            if (lane < E_) {
                ok = (avail[lane] > 0);
                sc = s_att[b * E_ + lane] + s_sb[lane] + s_eb[lane];
                sc = ok ? sc : -1e9f;
            }
            // width-16 max
            float m = sc;
#pragma unroll
            for (int o = 8; o > 0; o >>= 1) m = fmaxf(m, __shfl_xor_sync(0xffffffffu, m, o, 16));
            float ex = (lane < E_) ? __expf(sc - m) : 0.f;
            float sum = ex;
#pragma unroll
            for (int o = 8; o > 0; o >>= 1) sum += __shfl_xor_sync(0xffffffffu, sum, o, 16);
            float p = (lane < E_) ? (ex / sum) : 0.f;
            if (lane < E_) out[1 + b * E_ + lane] = p;
            float ps = fmaxf(p, 1e-10f);
            if (lane < E_) klacc += tprob * (logt - logf(ps));
            if (b == 0) {
                // first-occurrence argmax over lanes 0..15
                float pm = (lane < E_) ? p : -1.f;
                float mm = pm;
#pragma unroll
                for (int o = 16; o > 0; o >>= 1) mm = fmaxf(mm, __shfl_xor_sync(0xffffffffu, mm, o));
                unsigned bal = __ballot_sync(0xffffffffu, pm == mm);
                nidx = __ffs(bal) - 1;
            }
        }
        float kl = warp_sum(klacc);
        if (lane == 0) {
            out[0] = (kl / (float)B_) * 0.01f;
            out[1 + B_ * E_] = (float)nidx;
        }
    }
}

// ---------------- launch ----------------
extern "C" void kernel_launch(void* const* d_in, const int* in_sizes, int n_in,
                              void* d_out, int out_size) {
    const float* hid     = (const float*)d_in[0];
    const float* le      = (const float*)d_in[1];
    const float* ce      = (const float*)d_in[2];
    const float* spatial = (const float*)d_in[3];
    const float* edge    = (const float*)d_in[4];
    const float* gamma   = (const float*)d_in[5];
    const float* beta    = (const float*)d_in[6];
    const float* Wq      = (const float*)d_in[7];
    const float* bq      = (const float*)d_in[8];
    const float* Wk      = (const float*)d_in[9];
    const float* bk      = (const float*)d_in[10];
    // d_in[11], d_in[12] (Wv, bv) intentionally unused: v is dead in the reference
    const int*   curp    = (const int*)d_in[13];
    const int*   avail   = (const int*)d_in[14];
    float* out = (float*)d_out;

    kA<<<NBLK_A, 128>>>(hid);
    kB0<<<160, 256>>>(le, ce, gamma, beta, curp);
    kB<<<128, 256>>>(Wq, bq, Wk, bk);
    kC<<<1, 256>>>(spatial, edge, curp, avail, out);
}

// round 4
// speedup vs baseline: 1.4961x; 1.4961x over previous
#include <cuda_runtime.h>
#include <math.h>

#define B_ 4
#define S_ 4096
#define H_ 2048
#define E_ 16
#define ED_ 512
#define H4 (H_/4)          // 512 float4 per row
#define NBLK_A 512
#define WARPS_A 8          // per block (256 threads)
#define ROWS_PER_WARP 4    // 512*8*4 = 16384 = B*S
#define BLKS_PER_BATCH (NBLK_A / B_)   // 128
#define NBLK_B 128

// ---------------- device scratch (written fresh every launch) ----------------
__device__ float g_part[NBLK_A * H_];   // per-block LN partial sums (4 MB)
__device__ float g_qi[B_ * H_];         // query_input
__device__ float g_lf[E_ * H_];         // layer_features
__device__ float g_attp[NBLK_B * B_ * E_]; // per-block attention partials
__device__ int   g_ctr;                 // zero-init at load; reset by epilogue

__device__ __forceinline__ float warp_sum(float v) {
#pragma unroll
    for (int o = 16; o > 0; o >>= 1) v += __shfl_xor_sync(0xffffffffu, v, o);
    return v;
}
__device__ __forceinline__ float dot4(float4 a, float4 b) {
    return fmaf(a.x, b.x, fmaf(a.y, b.y, fmaf(a.z, b.z, a.w * b.w)));
}

// ---------------- Kernel A: LayerNorm + mean over S (partials) ----------------
__global__ void __launch_bounds__(256) kA(const float* __restrict__ hid) {
    __shared__ float sbuf[WARPS_A * H_];   // 64 KB
    const int warp = threadIdx.x >> 5, lane = threadIdx.x & 31;
    const long wg = (long)blockIdx.x * WARPS_A + warp;       // 0..4095
    const size_t row0 = (size_t)wg * ROWS_PER_WARP;

    float4 acc[16];
#pragma unroll
    for (int i = 0; i < 16; i++) acc[i] = make_float4(0.f, 0.f, 0.f, 0.f);

    for (int r = 0; r < ROWS_PER_WARP; r++) {
        const float4* p = reinterpret_cast<const float4*>(hid) + (row0 + r) * H4;
        float4 v[16];
        float s = 0.f, s2 = 0.f;
#pragma unroll
        for (int i = 0; i < 16; i++) {
            float4 t = p[i * 32 + lane];
            v[i] = t;
            s  += t.x + t.y + t.z + t.w;
            s2 += t.x * t.x + t.y * t.y + t.z * t.z + t.w * t.w;
        }
        s = warp_sum(s); s2 = warp_sum(s2);
        const float mu = s * (1.f / H_);
        const float var = s2 * (1.f / H_) - mu * mu;
        const float rr = rsqrtf(var + 1e-5f);
#pragma unroll
        for (int i = 0; i < 16; i++) {
            acc[i].x += (v[i].x - mu) * rr;
            acc[i].y += (v[i].y - mu) * rr;
            acc[i].z += (v[i].z - mu) * rr;
            acc[i].w += (v[i].w - mu) * rr;
        }
    }
    // stage per-warp partials in smem
    float4* sb4 = reinterpret_cast<float4*>(sbuf) + warp * H4;
#pragma unroll
    for (int i = 0; i < 16; i++) sb4[i * 32 + lane] = acc[i];
    __syncthreads();
    // reduce 8 warps -> g_part[blk]
    float4* out4 = reinterpret_cast<float4*>(g_part + (size_t)blockIdx.x * H_);
    const float4* sall = reinterpret_cast<const float4*>(sbuf);
    for (int i = threadIdx.x; i < H4; i += 256) {
        float4 a = sall[i];
#pragma unroll
        for (int w = 1; w < WARPS_A; w++) {
            float4 b = sall[w * H4 + i];
            a.x += b.x; a.y += b.y; a.z += b.z; a.w += b.w;
        }
        out4[i] = a;
    }
}

// ---------------- Kernel B0: reduce partials -> query_input; build lf ----------------
// blocks 0..15: qi (2 threads per float4 output, halves of c-range, shfl combine)
// blocks 16..47: lf = le + ce (float4)
__global__ void __launch_bounds__(256) kB0(const float* __restrict__ le,
                                           const float* __restrict__ ce,
                                           const float* __restrict__ gamma,
                                           const float* __restrict__ beta,
                                           const int* __restrict__ curp) {
    const int blk = blockIdx.x;
    if (blk < 16) {
        int g = blk * 256 + threadIdx.x;           // 0..4095
        int o = g >> 1, half = g & 1;              // o: 0..2047 float4 outputs
        int b = o >> 9, h4 = o & 511;
        const float4* gp = reinterpret_cast<const float4*>(g_part);
        size_t base = ((size_t)(b * BLKS_PER_BATCH + half * 64)) * H4 + h4;
        float4 s = make_float4(0.f, 0.f, 0.f, 0.f);
#pragma unroll 8
        for (int c = 0; c < 64; c++) {
            float4 t = gp[base + (size_t)c * H4];
            s.x += t.x; s.y += t.y; s.z += t.z; s.w += t.w;
        }
        s.x += __shfl_xor_sync(0xffffffffu, s.x, 1);
        s.y += __shfl_xor_sync(0xffffffffu, s.y, 1);
        s.z += __shfl_xor_sync(0xffffffffu, s.z, 1);
        s.w += __shfl_xor_sync(0xffffffffu, s.w, 1);
        if (half == 0) {
            const int cur = *curp;
            float4 g4 = reinterpret_cast<const float4*>(gamma)[h4];
            float4 b4 = reinterpret_cast<const float4*>(beta)[h4];
            float4 l4 = reinterpret_cast<const float4*>(le)[cur * H4 + h4];
            float4 r;
            r.x = l4.x + g4.x * (s.x * (1.f / S_)) + b4.x;
            r.y = l4.y + g4.y * (s.y * (1.f / S_)) + b4.y;
            r.z = l4.z + g4.z * (s.z * (1.f / S_)) + b4.z;
            r.w = l4.w + g4.w * (s.w * (1.f / S_)) + b4.w;
            reinterpret_cast<float4*>(g_qi)[b * H4 + h4] = r;
        }
    } else {
        int idx = (blk - 16) * 256 + threadIdx.x;  // 0..8191 float4
        float4 a = reinterpret_cast<const float4*>(le)[idx];
        float4 c = reinterpret_cast<const float4*>(ce)[idx];
        reinterpret_cast<float4*>(g_lf)[idx] =
            make_float4(a.x + c.x, a.y + c.y, a.z + c.z, a.w + c.w);
    }
}

// ---------------- Kernel B: fused q/k GEMV + attention partials + epilogue ----
__global__ void __launch_bounds__(256) kB(const float* __restrict__ Wq,
                                          const float* __restrict__ bq,
                                          const float* __restrict__ Wk,
                                          const float* __restrict__ bk,
                                          const float* __restrict__ spatial,
                                          const float* __restrict__ edge,
                                          const int* __restrict__ curp,
                                          const int* __restrict__ avail,
                                          float* __restrict__ out) {
    __shared__ float s_attp[8][B_ * E_];
    __shared__ float s_red[4][B_ * E_];
    __shared__ float s_att[B_ * E_];
    __shared__ float s_w[ED_];
    __shared__ float s_eb[E_];
    __shared__ float s_sb[E_];
    __shared__ int   s_last;

    const int tid = threadIdx.x, warp = tid >> 5, lane = tid & 31;
    const int wg = blockIdx.x * 8 + warp;        // 0..1023
    const int j0 = wg * 2;

    float aq0[B_], aq1[B_], ak0[E_], ak1[E_];
#pragma unroll
    for (int b = 0; b < B_; b++) { aq0[b] = 0.f; aq1[b] = 0.f; }
#pragma unroll
    for (int e = 0; e < E_; e++) { ak0[e] = 0.f; ak1[e] = 0.f; }

    const float4* wq0 = reinterpret_cast<const float4*>(Wq) + (size_t)j0 * H4;
    const float4* wq1 = wq0 + H4;
    const float4* wk0 = reinterpret_cast<const float4*>(Wk) + (size_t)j0 * H4;
    const float4* wk1 = wk0 + H4;
    const float4* qi = reinterpret_cast<const float4*>(g_qi);
    const float4* lf = reinterpret_cast<const float4*>(g_lf);

#pragma unroll 4
    for (int t = 0; t < 16; t++) {
        const int idx = t * 32 + lane;
        float4 a0 = wq0[idx], a1 = wq1[idx];
        float4 c0 = wk0[idx], c1 = wk1[idx];
#pragma unroll
        for (int b = 0; b < B_; b++) {
            float4 x = qi[b * H4 + idx];
            aq0[b] += dot4(a0, x);
            aq1[b] += dot4(a1, x);
        }
#pragma unroll
        for (int e = 0; e < E_; e++) {
            float4 x = lf[e * H4 + idx];
            ak0[e] += dot4(c0, x);
            ak1[e] += dot4(c1, x);
        }
    }
    // full reductions (all lanes get totals), add biases
    float q0[B_], q1[B_], k0[E_], k1[E_];
    const float bq0 = bq[j0], bq1 = bq[j0 + 1];
    const float bk0 = bk[j0], bk1 = bk[j0 + 1];
#pragma unroll
    for (int b = 0; b < B_; b++) {
        q0[b] = warp_sum(aq0[b]) + bq0;
        q1[b] = warp_sum(aq1[b]) + bq1;
    }
#pragma unroll
    for (int e = 0; e < E_; e++) {
        k0[e] = warp_sum(ak0[e]) + bk0;
        k1[e] = warp_sum(ak1[e]) + bk1;
    }
    // lane 0: partial attention contribution of these 2 columns
    if (lane == 0) {
        const float inv_sqrt_h = rsqrtf((float)H_);
#pragma unroll
        for (int b = 0; b < B_; b++)
#pragma unroll
            for (int e = 0; e < E_; e++)
                s_attp[warp][b * E_ + e] = (q0[b] * k0[e] + q1[b] * k1[e]) * inv_sqrt_h;
    }
    __syncthreads();
    if (tid < B_ * E_) {
        float s = 0.f;
#pragma unroll
        for (int w = 0; w < 8; w++) s += s_attp[w][tid];
        g_attp[blockIdx.x * (B_ * E_) + tid] = s;
    }
    __threadfence();
    __syncthreads();
    if (tid == 0) {
        int old = atomicAdd(&g_ctr, 1);
        s_last = (old == NBLK_B - 1) ? 1 : 0;
    }
    __syncthreads();
    if (!s_last) return;

    // ================= epilogue (last block only) =================
    const int cur = *curp;

    // reduce attention partials: 128 blocks x 64 outputs
    {
        int o = tid & 63, q = tid >> 6;   // 4 chunks of 32 blocks
        float s = 0.f;
#pragma unroll 8
        for (int c = 0; c < 32; c++) s += g_attp[(q * 32 + c) * (B_ * E_) + o];
        s_red[q][o] = s;
    }
    // edge weight vector: w = sum_i row_mask_i * scale_i * edge[i,:]
    for (int h = tid; h < ED_; h += 256) {
        float a = 0.f;
#pragma unroll
        for (int i = 0; i < E_; i++) {
            int d = abs(i - cur);
            float rm = (float)avail[i] * ((i != cur) ? 1.f : 0.f) * (1.f / (float)max(d, 1));
            a += rm * edge[i * ED_ + h];
        }
        s_w[h] = a;
    }
    if (tid < E_) s_sb[tid] = spatial[abs(tid - cur)];
    __syncthreads();
    if (tid < B_ * E_)
        s_att[tid] = s_red[0][tid] + s_red[1][tid] + s_red[2][tid] + s_red[3][tid];

    // edge_bias[j] = w . edge[j,:]; 8 warps x 2 outputs
    for (int jj = 0; jj < 2; jj++) {
        int j = warp * 2 + jj;
        float s = 0.f;
#pragma unroll
        for (int t = 0; t < 16; t++) s += s_w[t * 32 + lane] * edge[j * ED_ + t * 32 + lane];
        s = warp_sum(s);
        if (lane == 0) s_eb[j] = s;
    }
    __syncthreads();

    // finalize on warp 0
    if (warp == 0) {
        float av = (lane < E_) ? (float)avail[lane] : 0.f;
        float num_avail = warp_sum(av);
        float tprob = 1.f / num_avail;
        float logt = logf(tprob);
        float klacc = 0.f;
        int nidx = 0;
        for (int b = 0; b < B_; b++) {
            float sc = -1e30f;
            if (lane < E_) {
                bool ok = (avail[lane] > 0);
                sc = s_att[b * E_ + lane] + s_sb[lane] + s_eb[lane];
                sc = ok ? sc : -1e9f;
            }
            float m = sc;
#pragma unroll
            for (int o = 8; o > 0; o >>= 1) m = fmaxf(m, __shfl_xor_sync(0xffffffffu, m, o, 16));
            float ex = (lane < E_) ? __expf(sc - m) : 0.f;
            float sum = ex;
#pragma unroll
            for (int o = 8; o > 0; o >>= 1) sum += __shfl_xor_sync(0xffffffffu, sum, o, 16);
            float p = (lane < E_) ? (ex / sum) : 0.f;
            if (lane < E_) out[1 + b * E_ + lane] = p;
            float ps = fmaxf(p, 1e-10f);
            if (lane < E_) klacc += tprob * (logt - logf(ps));
            if (b == 0) {
                float pm = (lane < E_) ? p : -1.f;
                float mm = pm;
#pragma unroll
                for (int o = 16; o > 0; o >>= 1) mm = fmaxf(mm, __shfl_xor_sync(0xffffffffu, mm, o));
                unsigned bal = __ballot_sync(0xffffffffu, pm == mm);
                nidx = __ffs(bal) - 1;
            }
        }
        float kl = warp_sum(klacc);
        if (lane == 0) {
            out[0] = (kl / (float)B_) * 0.01f;
            out[1 + B_ * E_] = (float)nidx;
            g_ctr = 0;   // reset for next graph replay
        }
    }
}

// ---------------- launch ----------------
extern "C" void kernel_launch(void* const* d_in, const int* in_sizes, int n_in,
                              void* d_out, int out_size) {
    const float* hid     = (const float*)d_in[0];
    const float* le      = (const float*)d_in[1];
    const float* ce      = (const float*)d_in[2];
    const float* spatial = (const float*)d_in[3];
    const float* edge    = (const float*)d_in[4];
    const float* gamma   = (const float*)d_in[5];
    const float* beta    = (const float*)d_in[6];
    const float* Wq      = (const float*)d_in[7];
    const float* bq      = (const float*)d_in[8];
    const float* Wk      = (const float*)d_in[9];
    const float* bk      = (const float*)d_in[10];
    // d_in[11], d_in[12] (Wv, bv) intentionally unused: v is dead in the reference
    const int*   curp    = (const int*)d_in[13];
    const int*   avail   = (const int*)d_in[14];
    float* out = (float*)d_out;

    kA<<<NBLK_A, 256>>>(hid);
    kB0<<<48, 256>>>(le, ce, gamma, beta, curp);
    kB<<<NBLK_B, 256>>>(Wq, bq, Wk, bk, spatial, edge, curp, avail, out);
}

// round 6
// speedup vs baseline: 1.8119x; 1.2111x over previous
#include <cuda_runtime.h>
#include <math.h>

#define B_ 4
#define S_ 4096
#define H_ 2048
#define E_ 16
#define ED_ 512
#define H4 (H_/4)          // 512 float4 per row
#define NBLK_A 512
#define ROWS_PER_BLK_A 32
#define BLKS_PER_BATCH (NBLK_A / B_)   // 128
#define NBLK_B 256

// ---------------- device scratch (written fresh every launch) ----------------
__device__ float g_part[NBLK_A * H_];   // per-block LN partial sums (4 MB)
__device__ float g_qi[B_ * H_];         // query_input
__device__ float g_lf[E_ * H_];         // layer_features
__device__ float g_attp[NBLK_B * B_ * E_]; // per-block attention partials
__device__ int   g_ctr;                 // zero-init at load; reset by epilogue

__device__ __forceinline__ float warp_sum(float v) {
#pragma unroll
    for (int o = 16; o > 0; o >>= 1) v += __shfl_xor_sync(0xffffffffu, v, o);
    return v;
}
__device__ __forceinline__ float dot4(float4 a, float4 b) {
    return fmaf(a.x, b.x, fmaf(a.y, b.y, fmaf(a.z, b.z, a.w * b.w)));
}

// ---------------- Kernel A: LayerNorm + mean over S (partials) ----------------
// 4 warps cooperate on one row (quarter-row each): v[4]+acc[4] keeps regs ~64
// so 4 blocks/SM stay resident (50% occ) to saturate HBM.
__global__ void __launch_bounds__(256, 4) kA(const float* __restrict__ hid) {
    __shared__ float2 s_ms[8];           // per-warp (sum, sumsq)
    __shared__ float4 s_acc[8][128];     // 16 KB accumulator staging
    const int warp = threadIdx.x >> 5, lane = threadIdx.x & 31;
    const int qt = warp & 3;             // quarter of the row
    const int rg = warp >> 2;            // row-in-pair
    const size_t row0 = (size_t)blockIdx.x * ROWS_PER_BLK_A;

    float4 acc[4];
#pragma unroll
    for (int i = 0; i < 4; i++) acc[i] = make_float4(0.f, 0.f, 0.f, 0.f);

    for (int it = 0; it < 16; it++) {
        const size_t row = row0 + it * 2 + rg;
        const float4* p = reinterpret_cast<const float4*>(hid) + row * H4 + qt * 128;
        float4 v[4];
        float s = 0.f, s2 = 0.f;
#pragma unroll
        for (int i = 0; i < 4; i++) {
            float4 t = p[i * 32 + lane];
            v[i] = t;
            s  += t.x + t.y + t.z + t.w;
            s2 += t.x * t.x + t.y * t.y + t.z * t.z + t.w * t.w;
        }
        s = warp_sum(s); s2 = warp_sum(s2);
        if (lane == 0) s_ms[warp] = make_float2(s, s2);
        __syncthreads();
        float S = 0.f, S2 = 0.f;
#pragma unroll
        for (int q = 0; q < 4; q++) {
            float2 t = s_ms[rg * 4 + q];
            S += t.x; S2 += t.y;
        }
        __syncthreads();   // protect s_ms before next iteration's write
        const float mu = S * (1.f / H_);
        const float rr = rsqrtf(S2 * (1.f / H_) - mu * mu + 1e-5f);
#pragma unroll
        for (int i = 0; i < 4; i++) {
            acc[i].x += (v[i].x - mu) * rr;
            acc[i].y += (v[i].y - mu) * rr;
            acc[i].z += (v[i].z - mu) * rr;
            acc[i].w += (v[i].w - mu) * rr;
        }
    }
#pragma unroll
    for (int i = 0; i < 4; i++) s_acc[warp][i * 32 + lane] = acc[i];
    __syncthreads();
    float4* out4 = reinterpret_cast<float4*>(g_part) + (size_t)blockIdx.x * H4;
    for (int i = threadIdx.x; i < H4; i += 256) {
        const int q = i >> 7, idx = i & 127;
        float4 a = s_acc[q][idx], b = s_acc[q + 4][idx];
        out4[i] = make_float4(a.x + b.x, a.y + b.y, a.z + b.z, a.w + b.w);
    }
}

// ---------------- Kernel B0: reduce partials -> query_input; build lf --------
// blocks 0..63: qi. block = (b, 32-float4 chunk); warp reads 32 consecutive
// float4 per partial row (512B coalesced), 16 rows per thread, smem combine.
// blocks 64..95: lf = le + ce (float4).
__global__ void __launch_bounds__(256) kB0(const float* __restrict__ le,
                                           const float* __restrict__ ce,
                                           const float* __restrict__ gamma,
                                           const float* __restrict__ beta,
                                           const int* __restrict__ curp) {
    const int blk = blockIdx.x;
    if (blk < 64) {
        __shared__ float4 s_q[8][32];
        const int b = blk >> 4, chunk = blk & 15;
        const int lane = threadIdx.x & 31, csub = threadIdx.x >> 5;
        const int h4 = chunk * 32 + lane;
        const float4* gp = reinterpret_cast<const float4*>(g_part);
        size_t base = ((size_t)(b * BLKS_PER_BATCH + csub * 16)) * H4 + h4;
        float4 s = make_float4(0.f, 0.f, 0.f, 0.f);
#pragma unroll
        for (int c = 0; c < 16; c++) {
            float4 t = gp[base + (size_t)c * H4];
            s.x += t.x; s.y += t.y; s.z += t.z; s.w += t.w;
        }
        s_q[csub][lane] = s;
        __syncthreads();
        if (threadIdx.x < 32) {
            float4 t = s_q[0][lane];
#pragma unroll
            for (int q = 1; q < 8; q++) {
                float4 u = s_q[q][lane];
                t.x += u.x; t.y += u.y; t.z += u.z; t.w += u.w;
            }
            const int cur = *curp;
            float4 g4 = reinterpret_cast<const float4*>(gamma)[h4];
            float4 b4 = reinterpret_cast<const float4*>(beta)[h4];
            float4 l4 = reinterpret_cast<const float4*>(le)[cur * H4 + h4];
            float4 r;
            r.x = l4.x + g4.x * (t.x * (1.f / S_)) + b4.x;
            r.y = l4.y + g4.y * (t.y * (1.f / S_)) + b4.y;
            r.z = l4.z + g4.z * (t.z * (1.f / S_)) + b4.z;
            r.w = l4.w + g4.w * (t.w * (1.f / S_)) + b4.w;
            reinterpret_cast<float4*>(g_qi)[b * H4 + h4] = r;
        }
    } else {
        int idx = (blk - 64) * 256 + threadIdx.x;  // 0..8191 float4
        float4 a = reinterpret_cast<const float4*>(le)[idx];
        float4 c = reinterpret_cast<const float4*>(ce)[idx];
        reinterpret_cast<float4*>(g_lf)[idx] =
            make_float4(a.x + c.x, a.y + c.y, a.z + c.z, a.w + c.w);
    }
}

// ---------------- Kernel B: fused q/k GEMV + attention partials + epilogue ----
// 256 blocks x 128 threads; warp owns 2 output columns.
__global__ void __launch_bounds__(128) kB(const float* __restrict__ Wq,
                                          const float* __restrict__ bq,
                                          const float* __restrict__ Wk,
                                          const float* __restrict__ bk,
                                          const float* __restrict__ spatial,
                                          const float* __restrict__ edge,
                                          const int* __restrict__ curp,
                                          const int* __restrict__ avail,
                                          float* __restrict__ out) {
    __shared__ float s_attp[4][B_ * E_];
    __shared__ float s_red[2][B_ * E_];
    __shared__ float s_att[B_ * E_];
    __shared__ float s_w[ED_];
    __shared__ float s_eb[E_];
    __shared__ float s_sb[E_];
    __shared__ int   s_last;

    const int tid = threadIdx.x, warp = tid >> 5, lane = tid & 31;
    const int wg = blockIdx.x * 4 + warp;        // 0..1023
    const int j0 = wg * 2;

    float aq0[B_], aq1[B_], ak0[E_], ak1[E_];
#pragma unroll
    for (int b = 0; b < B_; b++) { aq0[b] = 0.f; aq1[b] = 0.f; }
#pragma unroll
    for (int e = 0; e < E_; e++) { ak0[e] = 0.f; ak1[e] = 0.f; }

    const float4* wq0 = reinterpret_cast<const float4*>(Wq) + (size_t)j0 * H4;
    const float4* wq1 = wq0 + H4;
    const float4* wk0 = reinterpret_cast<const float4*>(Wk) + (size_t)j0 * H4;
    const float4* wk1 = wk0 + H4;
    const float4* qi = reinterpret_cast<const float4*>(g_qi);
    const float4* lf = reinterpret_cast<const float4*>(g_lf);

#pragma unroll 4
    for (int t = 0; t < 16; t++) {
        const int idx = t * 32 + lane;
        float4 a0 = wq0[idx], a1 = wq1[idx];
        float4 c0 = wk0[idx], c1 = wk1[idx];
#pragma unroll
        for (int b = 0; b < B_; b++) {
            float4 x = qi[b * H4 + idx];
            aq0[b] += dot4(a0, x);
            aq1[b] += dot4(a1, x);
        }
#pragma unroll
        for (int e = 0; e < E_; e++) {
            float4 x = lf[e * H4 + idx];
            ak0[e] += dot4(c0, x);
            ak1[e] += dot4(c1, x);
        }
    }
    // full reductions (all lanes get totals), add biases
    float q0[B_], q1[B_], k0[E_], k1[E_];
    const float bq0 = bq[j0], bq1 = bq[j0 + 1];
    const float bk0 = bk[j0], bk1 = bk[j0 + 1];
#pragma unroll
    for (int b = 0; b < B_; b++) {
        q0[b] = warp_sum(aq0[b]) + bq0;
        q1[b] = warp_sum(aq1[b]) + bq1;
    }
#pragma unroll
    for (int e = 0; e < E_; e++) {
        k0[e] = warp_sum(ak0[e]) + bk0;
        k1[e] = warp_sum(ak1[e]) + bk1;
    }
    if (lane == 0) {
        const float inv_sqrt_h = rsqrtf((float)H_);
#pragma unroll
        for (int b = 0; b < B_; b++)
#pragma unroll
            for (int e = 0; e < E_; e++)
                s_attp[warp][b * E_ + e] = (q0[b] * k0[e] + q1[b] * k1[e]) * inv_sqrt_h;
    }
    __syncthreads();
    if (tid < B_ * E_) {
        float s = s_attp[0][tid] + s_attp[1][tid] + s_attp[2][tid] + s_attp[3][tid];
        g_attp[blockIdx.x * (B_ * E_) + tid] = s;
    }
    __threadfence();
    __syncthreads();
    if (tid == 0) {
        int old = atomicAdd(&g_ctr, 1);
        s_last = (old == NBLK_B - 1) ? 1 : 0;
    }
    __syncthreads();
    if (!s_last) return;

    // ================= epilogue (last block only, 128 threads) =================
    const int cur = *curp;

    // reduce attention partials: 256 blocks x 64 outputs (coalesced 256B rows)
    {
        int o = tid & 63, q = tid >> 6;   // 2 chunks of 128 blocks
        float s = 0.f;
#pragma unroll 8
        for (int c = 0; c < 128; c++) s += g_attp[(q * 128 + c) * (B_ * E_) + o];
        s_red[q][o] = s;
    }
    // edge weight vector: w = sum_i row_mask_i * scale_i * edge[i,:]
    for (int h = tid; h < ED_; h += 128) {
        float a = 0.f;
#pragma unroll
        for (int i = 0; i < E_; i++) {
            int d = abs(i - cur);
            float rm = (float)avail[i] * ((i != cur) ? 1.f : 0.f) * (1.f / (float)max(d, 1));
            a += rm * edge[i * ED_ + h];
        }
        s_w[h] = a;
    }
    if (tid < E_) s_sb[tid] = spatial[abs(tid - cur)];
    __syncthreads();
    if (tid < B_ * E_) s_att[tid] = s_red[0][tid] + s_red[1][tid];

    // edge_bias[j] = w . edge[j,:]; 4 warps x 4 outputs
    for (int jj = 0; jj < 4; jj++) {
        int j = warp * 4 + jj;
        float s = 0.f;
#pragma unroll
        for (int t = 0; t < 16; t++) s += s_w[t * 32 + lane] * edge[j * ED_ + t * 32 + lane];
        s = warp_sum(s);
        if (lane == 0) s_eb[j] = s;
    }
    __syncthreads();

    // finalize on warp 0
    if (warp == 0) {
        float av = (lane < E_) ? (float)avail[lane] : 0.f;
        float num_avail = warp_sum(av);
        float tprob = 1.f / num_avail;
        float logt = logf(tprob);
        float klacc = 0.f;
        int nidx = 0;
        for (int b = 0; b < B_; b++) {
            float sc = -1e30f;
            if (lane < E_) {
                bool ok = (avail[lane] > 0);
                sc = s_att[b * E_ + lane] + s_sb[lane] + s_eb[lane];
                sc = ok ? sc : -1e9f;
            }
            float m = sc;
#pragma unroll
            for (int o = 8; o > 0; o >>= 1) m = fmaxf(m, __shfl_xor_sync(0xffffffffu, m, o, 16));
            float ex = (lane < E_) ? __expf(sc - m) : 0.f;
            float sum = ex;
#pragma unroll
            for (int o = 8; o > 0; o >>= 1) sum += __shfl_xor_sync(0xffffffffu, sum, o, 16);
            float p = (lane < E_) ? (ex / sum) : 0.f;
            if (lane < E_) out[1 + b * E_ + lane] = p;
            float ps = fmaxf(p, 1e-10f);
            if (lane < E_) klacc += tprob * (logt - logf(ps));
            if (b == 0) {
                float pm = (lane < E_) ? p : -1.f;
                float mm = pm;
#pragma unroll
                for (int o = 16; o > 0; o >>= 1) mm = fmaxf(mm, __shfl_xor_sync(0xffffffffu, mm, o));
                unsigned bal = __ballot_sync(0xffffffffu, pm == mm);
                nidx = __ffs(bal) - 1;
            }
        }
        float kl = warp_sum(klacc);
        if (lane == 0) {
            out[0] = (kl / (float)B_) * 0.01f;
            out[1 + B_ * E_] = (float)nidx;
            g_ctr = 0;   // reset for next graph replay
        }
    }
}

// ---------------- launch ----------------
extern "C" void kernel_launch(void* const* d_in, const int* in_sizes, int n_in,
                              void* d_out, int out_size) {
    const float* hid     = (const float*)d_in[0];
    const float* le      = (const float*)d_in[1];
    const float* ce      = (const float*)d_in[2];
    const float* spatial = (const float*)d_in[3];
    const float* edge    = (const float*)d_in[4];
    const float* gamma   = (const float*)d_in[5];
    const float* beta    = (const float*)d_in[6];
    const float* Wq      = (const float*)d_in[7];
    const float* bq      = (const float*)d_in[8];
    const float* Wk      = (const float*)d_in[9];
    const float* bk      = (const float*)d_in[10];
    // d_in[11], d_in[12] (Wv, bv) intentionally unused: v is dead in the reference
    const int*   curp    = (const int*)d_in[13];
    const int*   avail   = (const int*)d_in[14];
    float* out = (float*)d_out;

    kA<<<NBLK_A, 256>>>(hid);
    kB0<<<96, 256>>>(le, ce, gamma, beta, curp);
    kB<<<NBLK_B, 128>>>(Wq, bq, Wk, bk, spatial, edge, curp, avail, out);
}

// round 7
// speedup vs baseline: 2.0720x; 1.1435x over previous
#include <cuda_runtime.h>
#include <math.h>
#include <string.h>

#define B_ 4
#define S_ 4096
#define H_ 2048
#define E_ 16
#define ED_ 512
#define H4 (H_/4)          // 512 float4 per row
#define NBLK_A 512
#define ROWS_PER_BLK_A 32
#define BLKS_PER_BATCH (NBLK_A / B_)   // 128
#define NBLK_B 256

// ---------------- device scratch (written fresh every launch) ----------------
__device__ float g_part[NBLK_A * H_];   // per-block LN partial sums (4 MB)
__device__ float g_qi[B_ * H_];         // query_input
__device__ float g_lf[E_ * H_];         // layer_features
__device__ float g_attp[NBLK_B * B_ * E_]; // per-block attention partials
__device__ int   g_ctr;                 // zero-init at load; reset by epilogue

__device__ __forceinline__ float warp_sum(float v) {
#pragma unroll
    for (int o = 16; o > 0; o >>= 1) v += __shfl_xor_sync(0xffffffffu, v, o);
    return v;
}

// packed f32x2 fma: d = a*b + c (elementwise on the two packed floats)
__device__ __forceinline__ unsigned long long ffma2(unsigned long long a,
                                                    unsigned long long b,
                                                    unsigned long long c) {
    unsigned long long d;
    asm("fma.rn.f32x2 %0, %1, %2, %3;" : "=l"(d) : "l"(a), "l"(b), "l"(c));
    return d;
}
__device__ __forceinline__ float pairsum(unsigned long long v) {
    float2 f; memcpy(&f, &v, 8);
    return f.x + f.y;
}

// ---------------- Kernel A: LayerNorm + mean over S (partials) ----------------
// 8 warps cooperate on one row (eighth-row each, 2 float4/thread).
// One barrier per row (double-buffered mean/var exchange), next-row loads
// prefetched before the barrier. ~40 regs -> 6 blocks/SM, single wave.
__global__ void __launch_bounds__(256, 6) kA(const float* __restrict__ hid) {
    __shared__ float2 s_ms[2][8];        // [parity][warp] (sum, sumsq)
    const int warp = threadIdx.x >> 5, lane = threadIdx.x & 31;
    const size_t row0 = (size_t)blockIdx.x * ROWS_PER_BLK_A;
    const int col = warp * 64 + lane;    // float4 index within row (+32 for second)

    float4 acc0 = make_float4(0.f, 0.f, 0.f, 0.f);
    float4 acc1 = make_float4(0.f, 0.f, 0.f, 0.f);

    const float4* base = reinterpret_cast<const float4*>(hid);
    // preload row 0
    float4 v0 = base[row0 * H4 + col];
    float4 v1 = base[row0 * H4 + col + 32];

    for (int r = 0; r < ROWS_PER_BLK_A; r++) {
        // prefetch next row (clamped on the very last row: redundant, harmless)
        const size_t prow = row0 + ((r < ROWS_PER_BLK_A - 1) ? (r + 1) : r);
        float4 n0 = base[prow * H4 + col];
        float4 n1 = base[prow * H4 + col + 32];

        float s  = v0.x + v0.y + v0.z + v0.w + v1.x + v1.y + v1.z + v1.w;
        float s2 = v0.x * v0.x + v0.y * v0.y + v0.z * v0.z + v0.w * v0.w
                 + v1.x * v1.x + v1.y * v1.y + v1.z * v1.z + v1.w * v1.w;
        s = warp_sum(s); s2 = warp_sum(s2);
        if (lane == 0) s_ms[r & 1][warp] = make_float2(s, s2);
        __syncthreads();
        float S = 0.f, S2 = 0.f;
#pragma unroll
        for (int w = 0; w < 8; w++) {
            float2 t = s_ms[r & 1][w];
            S += t.x; S2 += t.y;
        }
        const float mu = S * (1.f / H_);
        const float rr = rsqrtf(S2 * (1.f / H_) - mu * mu + 1e-5f);
        acc0.x += (v0.x - mu) * rr; acc0.y += (v0.y - mu) * rr;
        acc0.z += (v0.z - mu) * rr; acc0.w += (v0.w - mu) * rr;
        acc1.x += (v1.x - mu) * rr; acc1.y += (v1.y - mu) * rr;
        acc1.z += (v1.z - mu) * rr; acc1.w += (v1.w - mu) * rr;
        v0 = n0; v1 = n1;
    }
    float4* out4 = reinterpret_cast<float4*>(g_part) + (size_t)blockIdx.x * H4;
    out4[col] = acc0;
    out4[col + 32] = acc1;
}

// ---------------- Kernel B0: reduce partials -> query_input; build lf --------
__global__ void __launch_bounds__(256) kB0(const float* __restrict__ le,
                                           const float* __restrict__ ce,
                                           const float* __restrict__ gamma,
                                           const float* __restrict__ beta,
                                           const int* __restrict__ curp) {
    const int blk = blockIdx.x;
    if (blk < 64) {
        __shared__ float4 s_q[8][32];
        const int b = blk >> 4, chunk = blk & 15;
        const int lane = threadIdx.x & 31, csub = threadIdx.x >> 5;
        const int h4 = chunk * 32 + lane;
        const float4* gp = reinterpret_cast<const float4*>(g_part);
        size_t base = ((size_t)(b * BLKS_PER_BATCH + csub * 16)) * H4 + h4;
        float4 s = make_float4(0.f, 0.f, 0.f, 0.f);
#pragma unroll
        for (int c = 0; c < 16; c++) {
            float4 t = gp[base + (size_t)c * H4];
            s.x += t.x; s.y += t.y; s.z += t.z; s.w += t.w;
        }
        s_q[csub][lane] = s;
        __syncthreads();
        if (threadIdx.x < 32) {
            float4 t = s_q[0][lane];
#pragma unroll
            for (int q = 1; q < 8; q++) {
                float4 u = s_q[q][lane];
                t.x += u.x; t.y += u.y; t.z += u.z; t.w += u.w;
            }
            const int cur = *curp;
            float4 g4 = reinterpret_cast<const float4*>(gamma)[h4];
            float4 b4 = reinterpret_cast<const float4*>(beta)[h4];
            float4 l4 = reinterpret_cast<const float4*>(le)[cur * H4 + h4];
            float4 r;
            r.x = l4.x + g4.x * (t.x * (1.f / S_)) + b4.x;
            r.y = l4.y + g4.y * (t.y * (1.f / S_)) + b4.y;
            r.z = l4.z + g4.z * (t.z * (1.f / S_)) + b4.z;
            r.w = l4.w + g4.w * (t.w * (1.f / S_)) + b4.w;
            reinterpret_cast<float4*>(g_qi)[b * H4 + h4] = r;
        }
    } else {
        int idx = (blk - 64) * 256 + threadIdx.x;  // 0..8191 float4
        float4 a = reinterpret_cast<const float4*>(le)[idx];
        float4 c = reinterpret_cast<const float4*>(ce)[idx];
        reinterpret_cast<float4*>(g_lf)[idx] =
            make_float4(a.x + c.x, a.y + c.y, a.z + c.z, a.w + c.w);
    }
}

// ---------------- Kernel B: fused q/k GEMV + attention partials + epilogue ----
// 256 blocks x 128 threads; warp owns 2 output columns; packed f32x2 FMA.
__global__ void __launch_bounds__(128) kB(const float* __restrict__ Wq,
                                          const float* __restrict__ bq,
                                          const float* __restrict__ Wk,
                                          const float* __restrict__ bk,
                                          const float* __restrict__ spatial,
                                          const float* __restrict__ edge,
                                          const int* __restrict__ curp,
                                          const int* __restrict__ avail,
                                          float* __restrict__ out) {
    __shared__ float s_attp[4][B_ * E_];
    __shared__ float s_red[2][B_ * E_];
    __shared__ float s_att[B_ * E_];
    __shared__ float s_w[ED_];
    __shared__ float s_eb[E_];
    __shared__ float s_sb[E_];
    __shared__ int   s_last;

    const int tid = threadIdx.x, warp = tid >> 5, lane = tid & 31;
    const int wg = blockIdx.x * 4 + warp;        // 0..1023
    const int j0 = wg * 2;

    unsigned long long aq0[B_], aq1[B_], ak0[E_], ak1[E_];
#pragma unroll
    for (int b = 0; b < B_; b++) { aq0[b] = 0ull; aq1[b] = 0ull; }
#pragma unroll
    for (int e = 0; e < E_; e++) { ak0[e] = 0ull; ak1[e] = 0ull; }

    const ulonglong2* wq0 = reinterpret_cast<const ulonglong2*>(Wq) + (size_t)j0 * H4;
    const ulonglong2* wq1 = wq0 + H4;
    const ulonglong2* wk0 = reinterpret_cast<const ulonglong2*>(Wk) + (size_t)j0 * H4;
    const ulonglong2* wk1 = wk0 + H4;
    const ulonglong2* qi = reinterpret_cast<const ulonglong2*>(g_qi);
    const ulonglong2* lf = reinterpret_cast<const ulonglong2*>(g_lf);

#pragma unroll 2
    for (int t = 0; t < 16; t++) {
        const int idx = t * 32 + lane;
        ulonglong2 a0 = wq0[idx], a1 = wq1[idx];
        ulonglong2 c0 = wk0[idx], c1 = wk1[idx];
#pragma unroll
        for (int b = 0; b < B_; b++) {
            ulonglong2 x = qi[b * H4 + idx];
            aq0[b] = ffma2(a0.x, x.x, aq0[b]); aq0[b] = ffma2(a0.y, x.y, aq0[b]);
            aq1[b] = ffma2(a1.x, x.x, aq1[b]); aq1[b] = ffma2(a1.y, x.y, aq1[b]);
        }
#pragma unroll
        for (int e = 0; e < E_; e++) {
            ulonglong2 x = lf[e * H4 + idx];
            ak0[e] = ffma2(c0.x, x.x, ak0[e]); ak0[e] = ffma2(c0.y, x.y, ak0[e]);
            ak1[e] = ffma2(c1.x, x.x, ak1[e]); ak1[e] = ffma2(c1.y, x.y, ak1[e]);
        }
    }
    // full reductions (all lanes get totals), add biases
    float q0[B_], q1[B_], k0[E_], k1[E_];
    const float bq0 = bq[j0], bq1 = bq[j0 + 1];
    const float bk0 = bk[j0], bk1 = bk[j0 + 1];
#pragma unroll
    for (int b = 0; b < B_; b++) {
        q0[b] = warp_sum(pairsum(aq0[b])) + bq0;
        q1[b] = warp_sum(pairsum(aq1[b])) + bq1;
    }
#pragma unroll
    for (int e = 0; e < E_; e++) {
        k0[e] = warp_sum(pairsum(ak0[e])) + bk0;
        k1[e] = warp_sum(pairsum(ak1[e])) + bk1;
    }
    if (lane == 0) {
        const float inv_sqrt_h = rsqrtf((float)H_);
#pragma unroll
        for (int b = 0; b < B_; b++)
#pragma unroll
            for (int e = 0; e < E_; e++)
                s_attp[warp][b * E_ + e] = (q0[b] * k0[e] + q1[b] * k1[e]) * inv_sqrt_h;
    }
    __syncthreads();
    if (tid < B_ * E_) {
        float s = s_attp[0][tid] + s_attp[1][tid] + s_attp[2][tid] + s_attp[3][tid];
        g_attp[blockIdx.x * (B_ * E_) + tid] = s;
    }
    __threadfence();
    __syncthreads();
    if (tid == 0) {
        int old = atomicAdd(&g_ctr, 1);
        s_last = (old == NBLK_B - 1) ? 1 : 0;
    }
    __syncthreads();
    if (!s_last) return;

    // ================= epilogue (last block only, 128 threads) =================
    const int cur = *curp;
    {
        int o = tid & 63, q = tid >> 6;   // 2 chunks of 128 blocks
        float s = 0.f;
#pragma unroll 8
        for (int c = 0; c < 128; c++) s += g_attp[(q * 128 + c) * (B_ * E_) + o];
        s_red[q][o] = s;
    }
    for (int h = tid; h < ED_; h += 128) {
        float a = 0.f;
#pragma unroll
        for (int i = 0; i < E_; i++) {
            int d = abs(i - cur);
            float rm = (float)avail[i] * ((i != cur) ? 1.f : 0.f) * (1.f / (float)max(d, 1));
            a += rm * edge[i * ED_ + h];
        }
        s_w[h] = a;
    }
    if (tid < E_) s_sb[tid] = spatial[abs(tid - cur)];
    __syncthreads();
    if (tid < B_ * E_) s_att[tid] = s_red[0][tid] + s_red[1][tid];

    for (int jj = 0; jj < 4; jj++) {
        int j = warp * 4 + jj;
        float s = 0.f;
#pragma unroll
        for (int t = 0; t < 16; t++) s += s_w[t * 32 + lane] * edge[j * ED_ + t * 32 + lane];
        s = warp_sum(s);
        if (lane == 0) s_eb[j] = s;
    }
    __syncthreads();

    if (warp == 0) {
        float av = (lane < E_) ? (float)avail[lane] : 0.f;
        float num_avail = warp_sum(av);
        float tprob = 1.f / num_avail;
        float logt = logf(tprob);
        float klacc = 0.f;
        int nidx = 0;
        for (int b = 0; b < B_; b++) {
            float sc = -1e30f;
            if (lane < E_) {
                bool ok = (avail[lane] > 0);
                sc = s_att[b * E_ + lane] + s_sb[lane] + s_eb[lane];
                sc = ok ? sc : -1e9f;
            }
            float m = sc;
#pragma unroll
            for (int o = 8; o > 0; o >>= 1) m = fmaxf(m, __shfl_xor_sync(0xffffffffu, m, o, 16));
            float ex = (lane < E_) ? __expf(sc - m) : 0.f;
            float sum = ex;
#pragma unroll
            for (int o = 8; o > 0; o >>= 1) sum += __shfl_xor_sync(0xffffffffu, sum, o, 16);
            float p = (lane < E_) ? (ex / sum) : 0.f;
            if (lane < E_) out[1 + b * E_ + lane] = p;
            float ps = fmaxf(p, 1e-10f);
            if (lane < E_) klacc += tprob * (logt - logf(ps));
            if (b == 0) {
                float pm = (lane < E_) ? p : -1.f;
                float mm = pm;
#pragma unroll
                for (int o = 16; o > 0; o >>= 1) mm = fmaxf(mm, __shfl_xor_sync(0xffffffffu, mm, o));
                unsigned bal = __ballot_sync(0xffffffffu, pm == mm);
                nidx = __ffs(bal) - 1;
            }
        }
        float kl = warp_sum(klacc);
        if (lane == 0) {
            out[0] = (kl / (float)B_) * 0.01f;
            out[1 + B_ * E_] = (float)nidx;
            g_ctr = 0;   // reset for next graph replay
        }
    }
}

// ---------------- launch ----------------
extern "C" void kernel_launch(void* const* d_in, const int* in_sizes, int n_in,
                              void* d_out, int out_size) {
    const float* hid     = (const float*)d_in[0];
    const float* le      = (const float*)d_in[1];
    const float* ce      = (const float*)d_in[2];
    const float* spatial = (const float*)d_in[3];
    const float* edge    = (const float*)d_in[4];
    const float* gamma   = (const float*)d_in[5];
    const float* beta    = (const float*)d_in[6];
    const float* Wq      = (const float*)d_in[7];
    const float* bq      = (const float*)d_in[8];
    const float* Wk      = (const float*)d_in[9];
    const float* bk      = (const float*)d_in[10];
    // d_in[11], d_in[12] (Wv, bv) intentionally unused: v is dead in the reference
    const int*   curp    = (const int*)d_in[13];
    const int*   avail   = (const int*)d_in[14];
    float* out = (float*)d_out;

    kA<<<NBLK_A, 256>>>(hid);
    kB0<<<96, 256>>>(le, ce, gamma, beta, curp);
    kB<<<NBLK_B, 128>>>(Wq, bq, Wk, bk, spatial, edge, curp, avail, out);
}